// round 3
// baseline (speedup 1.0000x reference)
#include <cuda_runtime.h>
#include <cstdint>

#define B_  64
#define T_  2048
#define I_  256
#define H_  256
#define G3_ 768

// 402 MB scratch for precomputed input gates: layout [t][b][768]
__device__ float g_Gi[(size_t)B_ * T_ * G3_];

// ======================= Phase 1: Gi = x @ W_ih^T + b_ih =======================
#define BM 128
#define BN 64
#define BK 32
#define PAD 36

__global__ __launch_bounds__(256) void gi_gemm(
    const float* __restrict__ x, const float* __restrict__ W_ih,
    const float* __restrict__ b_ih, const int* __restrict__ lengths)
{
    const int m0    = blockIdx.x * BM;        // row = b*T + t
    const int batch = m0 >> 11;               // 2048 rows per batch, 128 | 2048
    const int t0    = m0 & (T_ - 1);
    if (t0 >= __ldg(&lengths[batch])) return; // whole tile masked -> skip
    const int n0 = blockIdx.y * BN;

    __shared__ float As[BM][PAD];
    __shared__ float Bs[BN][PAD];

    const int tid = threadIdx.x;
    const int tx = tid & 15, ty = tid >> 4;   // 16 x 16 -> thread tile 8(m) x 4(n)

    float acc[8][4];
#pragma unroll
    for (int i = 0; i < 8; i++)
#pragma unroll
        for (int c = 0; c < 4; c++) acc[i][c] = 0.f;

    for (int kt = 0; kt < I_; kt += BK) {
#pragma unroll
        for (int j = 0; j < 4; j++) {
            int idx = tid + j * 256;
            int row = idx >> 3, kp = idx & 7;
            float4 v = *(const float4*)&x[(size_t)(m0 + row) * I_ + kt + kp * 4];
            *(float4*)&As[row][kp * 4] = v;
        }
#pragma unroll
        for (int j = 0; j < 2; j++) {
            int idx = tid + j * 256;
            int row = idx >> 3, kp = idx & 7;
            float4 v = *(const float4*)&W_ih[(size_t)(n0 + row) * I_ + kt + kp * 4];
            *(float4*)&Bs[row][kp * 4] = v;
        }
        __syncthreads();
#pragma unroll
        for (int k = 0; k < BK; k++) {
            float a[8], b[4];
#pragma unroll
            for (int i = 0; i < 8; i++) a[i] = As[ty * 8 + i][k];
#pragma unroll
            for (int c = 0; c < 4; c++) b[c] = Bs[tx * 4 + c][k];
#pragma unroll
            for (int i = 0; i < 8; i++)
#pragma unroll
                for (int c = 0; c < 4; c++) acc[i][c] += a[i] * b[c];
        }
        __syncthreads();
    }

#pragma unroll
    for (int i = 0; i < 8; i++) {
        int t = t0 + ty * 8 + i;
        int n = n0 + tx * 4;
        float4 v;
        v.x = acc[i][0] + b_ih[n + 0];
        v.y = acc[i][1] + b_ih[n + 1];
        v.z = acc[i][2] + b_ih[n + 2];
        v.w = acc[i][3] + b_ih[n + 3];
        *(float4*)&g_Gi[((size_t)t * B_ + batch) * G3_ + n] = v;
    }
}

// ======================= Phase 2: recurrence =======================
// 16 clusters of 8 CTAs. Cluster c handles batches {4c..4c+3}.
// CTA rank r owns H-columns [r*32, r*32+32) for all 3 gates (96 W rows).
// Warp (rg, kc): rg = warp/8 in 0..2 (gate), kc = warp%8 (32-wide k chunk).
//   lane = output row within gate; W[row][kc*32..+32] lives in 32 REGISTERS
//   (16 x f32x2). h reads are WARP-UNIFORM BROADCASTS (1 wavefront each).
// Cross-warp k-reduction via tiny SMEM partial buffer ghp[gate][kc][b][lane].
// h (4 batches x 256) replicated per CTA, double-buffered, updated via
// DSMEM scalar stores + one cluster barrier per step.

#define REC_THREADS 768

__device__ __forceinline__ float sigm(float v) { return 1.f / (1.f + __expf(-v)); }

__device__ __forceinline__ unsigned long long fma2(unsigned long long a,
                                                   unsigned long long b,
                                                   unsigned long long c) {
    unsigned long long d;
    asm("fma.rn.f32x2 %0, %1, %2, %3;" : "=l"(d) : "l"(a), "l"(b), "l"(c));
    return d;
}
__device__ __forceinline__ unsigned long long packf2(float lo, float hi) {
    unsigned long long d;
    asm("mov.b64 %0, {%1, %2};" : "=l"(d) : "f"(lo), "f"(hi));
    return d;
}
__device__ __forceinline__ float unpack_sum(unsigned long long v) {
    float lo, hi;
    asm("mov.b64 {%0, %1}, %2;" : "=f"(lo), "=f"(hi) : "l"(v));
    return lo + hi;
}

__global__ void __cluster_dims__(8, 1, 1) __launch_bounds__(REC_THREADS, 1)
gru_rec(const float* __restrict__ att, const int* __restrict__ lengths,
        const float* __restrict__ W_hh, const float* __restrict__ b_hh,
        float* __restrict__ out)
{
    __shared__ alignas(16) float hb[2][4][256];   // [buf][batch][col], plain layout
    __shared__ float ghp[3][8][4][32];            // [gate][kc][batch][lane] partials

    uint32_t rank;
    asm("mov.u32 %0, %%cluster_ctarank;" : "=r"(rank));
    const int cid = blockIdx.x >> 3;
    const int b0  = cid * 4;

    const int tid  = threadIdx.x;
    const int warp = tid >> 5;
    const int lane = tid & 31;
    const int rg   = warp >> 3;        // gate 0..2
    const int kc   = warp & 7;         // k chunk: k in [kc*32, kc*32+32)

    // ---- W slice into registers: row = gate*256 + rank*32 + lane ----
    const int grow = rg * 256 + (int)rank * 32 + lane;
    unsigned long long wq[16];
#pragma unroll
    for (int i = 0; i < 8; i++) {
        float4 v = *(const float4*)&W_hh[(size_t)grow * H_ + kc * 32 + i * 4];
        wq[2 * i + 0] = packf2(v.x, v.y);
        wq[2 * i + 1] = packf2(v.z, v.w);
    }

    // ---- zero h buffer 0 ----
    for (int i = tid; i < 4 * 256; i += REC_THREADS) ((float*)hb[0])[i] = 0.f;

    // ---- gate-thread constants (threads 0..127: b = tid>>5, j = tid&31) ----
    const int gb  = tid >> 5;
    const int gj  = tid & 31;
    const int col = (int)rank * 32 + gj;
    const int myb = b0 + gb;
    float bhr = 0.f, bhz = 0.f, bhn = 0.f;
    int mylen = 0;
    if (tid < 128) {
        bhr = b_hh[col];
        bhz = b_hh[256 + col];
        bhn = b_hh[512 + col];
        mylen = lengths[myb];
    }
    const int Tmax = max(max(__ldg(&lengths[b0]),     __ldg(&lengths[b0 + 1])),
                         max(__ldg(&lengths[b0 + 2]), __ldg(&lengths[b0 + 3])));

    __syncthreads();

    for (int t = 0; t < Tmax; t++) {
        const int cur = t & 1, nxt = cur ^ 1;

        // prefetch gi + attention weight (DRAM latency hidden under matvec)
        float gir = 0.f, giz = 0.f, gin = 0.f, wt = 0.f;
        if (tid < 128) {
            const size_t base = ((size_t)t * B_ + myb) * G3_;
            gir = __ldg(&g_Gi[base + col]);
            giz = __ldg(&g_Gi[base + 256 + col]);
            gin = __ldg(&g_Gi[base + 512 + col]);
            wt  = __ldg(&att[(size_t)myb * T_ + t]);
        }

        // ---- matvec: broadcast-h, W in regs, packed f32x2 FMAs ----
        unsigned long long a0 = 0ull, a1 = 0ull, a2 = 0ull, a3 = 0ull;
        {
            const double2* h0 = (const double2*)&hb[cur][0][kc * 32];
            const double2* h1 = (const double2*)&hb[cur][1][kc * 32];
            const double2* h2 = (const double2*)&hb[cur][2][kc * 32];
            const double2* h3 = (const double2*)&hb[cur][3][kc * 32];
#pragma unroll
            for (int i = 0; i < 8; i++) {
                double2 v0 = h0[i];   // warp-uniform address -> broadcast
                double2 v1 = h1[i];
                double2 v2 = h2[i];
                double2 v3 = h3[i];
                a0 = fma2(wq[2*i],   __double_as_longlong(v0.x), a0);
                a1 = fma2(wq[2*i],   __double_as_longlong(v1.x), a1);
                a2 = fma2(wq[2*i],   __double_as_longlong(v2.x), a2);
                a3 = fma2(wq[2*i],   __double_as_longlong(v3.x), a3);
                a0 = fma2(wq[2*i+1], __double_as_longlong(v0.y), a0);
                a1 = fma2(wq[2*i+1], __double_as_longlong(v1.y), a1);
                a2 = fma2(wq[2*i+1], __double_as_longlong(v2.y), a2);
                a3 = fma2(wq[2*i+1], __double_as_longlong(v3.y), a3);
            }
        }
        // partials: lane = row-within-gate; conflict-free stride-1 stores
        ghp[rg][kc][0][lane] = unpack_sum(a0);
        ghp[rg][kc][1][lane] = unpack_sum(a1);
        ghp[rg][kc][2][lane] = unpack_sum(a2);
        ghp[rg][kc][3][lane] = unpack_sum(a3);
        __syncthreads();

        // ---- gates (128 threads) + DSMEM broadcast of own 32-col slice ----
        if (tid < 128) {
            float sr_ = 0.f, sz_ = 0.f, sn_ = 0.f;
#pragma unroll
            for (int k = 0; k < 8; k++) {
                sr_ += ghp[0][k][gb][gj];
                sz_ += ghp[1][k][gb][gj];
                sn_ += ghp[2][k][gb][gj];
            }
            const float hprev = hb[cur][gb][col];
            const float r = sigm(gir + sr_ + bhr);
            const float z = sigm(giz + sz_ + bhz);
            const float n = tanhf(gin + r * (sn_ + bhn));
            const float hnew = (1.f - z) * n + z * hprev;
            const float hg   = wt * hnew + (1.f - wt) * hprev;
            const float hv   = (t < mylen) ? hg : hprev;

            uint32_t laddr = (uint32_t)__cvta_generic_to_shared(
                (const void*)&hb[nxt][gb][col]);
#pragma unroll
            for (int rdst = 0; rdst < 8; rdst++) {
                uint32_t raddr;
                asm volatile("mapa.shared::cluster.u32 %0, %1, %2;"
                             : "=r"(raddr) : "r"(laddr), "r"(rdst));
                asm volatile("st.shared::cluster.f32 [%0], %1;"
                             :: "r"(raddr), "f"(hv) : "memory");
            }
        }

        // one cluster barrier per step (release/acquire orders DSMEM stores)
        asm volatile("barrier.cluster.arrive.aligned;" ::: "memory");
        asm volatile("barrier.cluster.wait.aligned;" ::: "memory");
    }

    if (tid < 128) out[(size_t)myb * H_ + col] = hb[Tmax & 1][gb][col];
}

// ======================= launch =======================
extern "C" void kernel_launch(void* const* d_in, const int* in_sizes, int n_in,
                              void* d_out, int out_size)
{
    const float* x       = (const float*)d_in[0];
    const float* att     = (const float*)d_in[1];
    const int*   lengths = (const int*)  d_in[2];
    const float* W_ih    = (const float*)d_in[3];
    const float* W_hh    = (const float*)d_in[4];
    const float* b_ih    = (const float*)d_in[5];
    const float* b_hh    = (const float*)d_in[6];
    float* out = (float*)d_out;
    (void)in_sizes; (void)n_in; (void)out_size;

    dim3 ggrid((B_ * T_) / BM, G3_ / BN);
    gi_gemm<<<ggrid, 256>>>(x, W_ih, b_ih, lengths);
    gru_rec<<<128, REC_THREADS>>>(att, lengths, W_hh, b_hh, out);
}

// round 4
// speedup vs baseline: 1.8285x; 1.8285x over previous
#include <cuda_runtime.h>
#include <cstdint>

#define B_  64
#define T_  2048
#define I_  256
#define H_  256
#define G3_ 768

// 402 MB scratch for precomputed input gates: layout [t][b][768]
__device__ float g_Gi[(size_t)B_ * T_ * G3_];

// ======================= Phase 1: Gi = x @ W_ih^T + b_ih =======================
#define BM 128
#define BN 64
#define BK 32
#define PAD 36

__global__ __launch_bounds__(256) void gi_gemm(
    const float* __restrict__ x, const float* __restrict__ W_ih,
    const float* __restrict__ b_ih, const int* __restrict__ lengths)
{
    const int m0    = blockIdx.x * BM;        // row = b*T + t
    const int batch = m0 >> 11;               // 2048 rows per batch, 128 | 2048
    const int t0    = m0 & (T_ - 1);
    if (t0 >= __ldg(&lengths[batch])) return; // whole tile masked -> skip
    const int n0 = blockIdx.y * BN;

    __shared__ float As[BM][PAD];
    __shared__ float Bs[BN][PAD];

    const int tid = threadIdx.x;
    const int tx = tid & 15, ty = tid >> 4;   // 16 x 16 -> thread tile 8(m) x 4(n)

    float acc[8][4];
#pragma unroll
    for (int i = 0; i < 8; i++)
#pragma unroll
        for (int c = 0; c < 4; c++) acc[i][c] = 0.f;

    for (int kt = 0; kt < I_; kt += BK) {
#pragma unroll
        for (int j = 0; j < 4; j++) {
            int idx = tid + j * 256;
            int row = idx >> 3, kp = idx & 7;
            float4 v = *(const float4*)&x[(size_t)(m0 + row) * I_ + kt + kp * 4];
            *(float4*)&As[row][kp * 4] = v;
        }
#pragma unroll
        for (int j = 0; j < 2; j++) {
            int idx = tid + j * 256;
            int row = idx >> 3, kp = idx & 7;
            float4 v = *(const float4*)&W_ih[(size_t)(n0 + row) * I_ + kt + kp * 4];
            *(float4*)&Bs[row][kp * 4] = v;
        }
        __syncthreads();
#pragma unroll
        for (int k = 0; k < BK; k++) {
            float a[8], b[4];
#pragma unroll
            for (int i = 0; i < 8; i++) a[i] = As[ty * 8 + i][k];
#pragma unroll
            for (int c = 0; c < 4; c++) b[c] = Bs[tx * 4 + c][k];
#pragma unroll
            for (int i = 0; i < 8; i++)
#pragma unroll
                for (int c = 0; c < 4; c++) acc[i][c] += a[i] * b[c];
        }
        __syncthreads();
    }

#pragma unroll
    for (int i = 0; i < 8; i++) {
        int t = t0 + ty * 8 + i;
        int n = n0 + tx * 4;
        float4 v;
        v.x = acc[i][0] + b_ih[n + 0];
        v.y = acc[i][1] + b_ih[n + 1];
        v.z = acc[i][2] + b_ih[n + 2];
        v.w = acc[i][3] + b_ih[n + 3];
        *(float4*)&g_Gi[((size_t)t * B_ + batch) * G3_ + n] = v;
    }
}

// ======================= Phase 2: recurrence =======================
// 16 clusters of 8 CTAs, batches {4c..4c+3} per cluster.
// CTA rank r owns H-columns [r*32, r*32+32) for all 3 gates (96 W rows),
// W in registers (16 f32x2/thread), h reads are warp-uniform broadcasts.
// SYNC (new): no per-step cluster barrier. h exchange via st.async.b64
// (packed col pairs) signaling the destination CTA's phase mbarrier
// (tx-count 4096 B = 8 src CTAs x 128 cols x 4 B). Consumers
// try_wait.parity.acquire.cluster. Double-buffered hb + 2 mbarriers;
// "store-follows-read" ordering makes the 2-deep pipeline safe.

#define REC_THREADS 768
#define EXP_TX 4096

__device__ __forceinline__ float sigm(float v) { return 1.f / (1.f + __expf(-v)); }

__device__ __forceinline__ unsigned long long fma2(unsigned long long a,
                                                   unsigned long long b,
                                                   unsigned long long c) {
    unsigned long long d;
    asm("fma.rn.f32x2 %0, %1, %2, %3;" : "=l"(d) : "l"(a), "l"(b), "l"(c));
    return d;
}
__device__ __forceinline__ unsigned long long packf2(float lo, float hi) {
    unsigned long long d;
    asm("mov.b64 %0, {%1, %2};" : "=l"(d) : "f"(lo), "f"(hi));
    return d;
}
__device__ __forceinline__ float unpack_sum(unsigned long long v) {
    float lo, hi;
    asm("mov.b64 {%0, %1}, %2;" : "=f"(lo), "=f"(hi) : "l"(v));
    return lo + hi;
}
__device__ __forceinline__ void mbar_wait_cluster(uint32_t mbar, uint32_t parity) {
    uint32_t done;
    asm volatile(
        "{\n\t.reg .pred p;\n\t"
        "mbarrier.try_wait.parity.acquire.cluster.shared::cta.b64 p, [%1], %2;\n\t"
        "selp.b32 %0, 1, 0, p;\n\t}"
        : "=r"(done) : "r"(mbar), "r"(parity) : "memory");
    while (!done) {
        asm volatile(
            "{\n\t.reg .pred p;\n\t"
            "mbarrier.try_wait.parity.acquire.cluster.shared::cta.b64 p, [%1], %2, 0x989680;\n\t"
            "selp.b32 %0, 1, 0, p;\n\t}"
            : "=r"(done) : "r"(mbar), "r"(parity) : "memory");
    }
}

__global__ void __cluster_dims__(8, 1, 1) __launch_bounds__(REC_THREADS, 1)
gru_rec(const float* __restrict__ att, const int* __restrict__ lengths,
        const float* __restrict__ W_hh, const float* __restrict__ b_hh,
        float* __restrict__ out)
{
    __shared__ alignas(16) float hb[2][4][256];   // [buf][batch][col]
    __shared__ float ghp[3][8][4][32];            // [gate][kc][batch][lane] partials
    __shared__ alignas(8) unsigned long long mbar[2];

    uint32_t rank;
    asm("mov.u32 %0, %%cluster_ctarank;" : "=r"(rank));
    const int cid = blockIdx.x >> 3;
    const int b0  = cid * 4;

    const int tid  = threadIdx.x;
    const int warp = tid >> 5;
    const int lane = tid & 31;
    const int rg   = warp >> 3;        // gate 0..2
    const int kc   = warp & 7;         // k chunk: k in [kc*32, kc*32+32)

    // ---- W slice into registers: row = gate*256 + rank*32 + lane ----
    const int grow = rg * 256 + (int)rank * 32 + lane;
    unsigned long long wq[16];
#pragma unroll
    for (int i = 0; i < 8; i++) {
        float4 v = *(const float4*)&W_hh[(size_t)grow * H_ + kc * 32 + i * 4];
        wq[2 * i + 0] = packf2(v.x, v.y);
        wq[2 * i + 1] = packf2(v.z, v.w);
    }

    // ---- zero h buffer 0, init mbarriers ----
    for (int i = tid; i < 4 * 256; i += REC_THREADS) ((float*)hb[0])[i] = 0.f;
    if (tid == 0) {
        uint32_t m0 = (uint32_t)__cvta_generic_to_shared(&mbar[0]);
        uint32_t m1 = (uint32_t)__cvta_generic_to_shared(&mbar[1]);
        asm volatile("mbarrier.init.shared.b64 [%0], 1;" :: "r"(m0) : "memory");
        asm volatile("mbarrier.init.shared.b64 [%0], 1;" :: "r"(m1) : "memory");
    }

    // ---- gate-thread constants (threads 0..127: b = tid>>5, j = tid&31) ----
    const int gb  = tid >> 5;
    const int gj  = tid & 31;
    const int col = (int)rank * 32 + gj;
    const int myb = b0 + gb;
    float bhr = 0.f, bhz = 0.f, bhn = 0.f;
    int mylen = 0;
    if (tid < 128) {
        bhr = b_hh[col];
        bhz = b_hh[256 + col];
        bhn = b_hh[512 + col];
        mylen = lengths[myb];
    }
    const int Tmax = max(max(__ldg(&lengths[b0]),     __ldg(&lengths[b0 + 1])),
                         max(__ldg(&lengths[b0 + 2]), __ldg(&lengths[b0 + 3])));

    __syncthreads();
    // all CTAs: buffers zeroed + mbars inited before any remote store can arrive
    asm volatile("barrier.cluster.arrive.aligned;" ::: "memory");
    asm volatile("barrier.cluster.wait.aligned;" ::: "memory");

    uint32_t ph0 = 0, ph1 = 0;

    for (int t = 0; t < Tmax; t++) {
        const int cur = t & 1, nxt = cur ^ 1;

        // gi prefetch first: no h dependency, hides DRAM latency under wait+matvec
        float gir = 0.f, giz = 0.f, gin = 0.f, wt = 0.f;
        if (tid < 128) {
            const size_t base = ((size_t)t * B_ + myb) * G3_;
            gir = __ldg(&g_Gi[base + col]);
            giz = __ldg(&g_Gi[base + 256 + col]);
            gin = __ldg(&g_Gi[base + 512 + col]);
            wt  = __ldg(&att[(size_t)myb * T_ + t]);
        }

        // arm the buffer we will write this step (its previous phase completed
        // at step t-1's wait; posting here is ~1 matvec ahead of any tx)
        if (tid == 0) {
            uint32_t mn = (uint32_t)__cvta_generic_to_shared(&mbar[nxt]);
            asm volatile("mbarrier.arrive.expect_tx.shared.b64 _, [%0], %1;"
                         :: "r"(mn), "n"(EXP_TX) : "memory");
        }

        // wait for h_t (all threads)
        if (t > 0) {
            uint32_t mc = (uint32_t)__cvta_generic_to_shared(&mbar[cur]);
            mbar_wait_cluster(mc, cur ? ph1 : ph0);
            if (cur) ph1 ^= 1; else ph0 ^= 1;
        }

        // ---- matvec: broadcast-h, W in regs, packed f32x2 FMAs ----
        unsigned long long a0 = 0ull, a1 = 0ull, a2 = 0ull, a3 = 0ull;
        {
            const double2* h0 = (const double2*)&hb[cur][0][kc * 32];
            const double2* h1 = (const double2*)&hb[cur][1][kc * 32];
            const double2* h2 = (const double2*)&hb[cur][2][kc * 32];
            const double2* h3 = (const double2*)&hb[cur][3][kc * 32];
#pragma unroll
            for (int i = 0; i < 8; i++) {
                double2 v0 = h0[i];   // warp-uniform address -> broadcast
                double2 v1 = h1[i];
                double2 v2 = h2[i];
                double2 v3 = h3[i];
                a0 = fma2(wq[2*i],   __double_as_longlong(v0.x), a0);
                a1 = fma2(wq[2*i],   __double_as_longlong(v1.x), a1);
                a2 = fma2(wq[2*i],   __double_as_longlong(v2.x), a2);
                a3 = fma2(wq[2*i],   __double_as_longlong(v3.x), a3);
                a0 = fma2(wq[2*i+1], __double_as_longlong(v0.y), a0);
                a1 = fma2(wq[2*i+1], __double_as_longlong(v1.y), a1);
                a2 = fma2(wq[2*i+1], __double_as_longlong(v2.y), a2);
                a3 = fma2(wq[2*i+1], __double_as_longlong(v3.y), a3);
            }
        }
        ghp[rg][kc][0][lane] = unpack_sum(a0);
        ghp[rg][kc][1][lane] = unpack_sum(a1);
        ghp[rg][kc][2][lane] = unpack_sum(a2);
        ghp[rg][kc][3][lane] = unpack_sum(a3);
        __syncthreads();

        // ---- gates (128 threads) + st.async broadcast of own 32-col slice ----
        if (tid < 128) {
            float sr_ = 0.f, sz_ = 0.f, sn_ = 0.f;
#pragma unroll
            for (int k = 0; k < 8; k++) {
                sr_ += ghp[0][k][gb][gj];
                sz_ += ghp[1][k][gb][gj];
                sn_ += ghp[2][k][gb][gj];
            }
            const float hprev = hb[cur][gb][col];
            const float r = sigm(gir + sr_ + bhr);
            const float z = sigm(giz + sz_ + bhz);
            const float n = tanhf(gin + r * (sn_ + bhn));
            const float hnew = (1.f - z) * n + z * hprev;
            const float hg   = wt * hnew + (1.f - wt) * hprev;
            const float hv   = (t < mylen) ? hg : hprev;

            // pack col pairs: even lane stores (hv[col], hv[col+1]) as b64
            const float hvo = __shfl_xor_sync(0xffffffffu, hv, 1);
            if ((gj & 1) == 0) {
                const unsigned long long pk = packf2(hv, hvo);
                uint32_t lh = (uint32_t)__cvta_generic_to_shared(
                    (const void*)&hb[nxt][gb][col]);
                uint32_t lm = (uint32_t)__cvta_generic_to_shared(&mbar[nxt]);
#pragma unroll
                for (int rdst = 0; rdst < 8; rdst++) {
                    uint32_t rh, rm;
                    asm volatile("mapa.shared::cluster.u32 %0, %1, %2;"
                                 : "=r"(rh) : "r"(lh), "r"(rdst));
                    asm volatile("mapa.shared::cluster.u32 %0, %1, %2;"
                                 : "=r"(rm) : "r"(lm), "r"(rdst));
                    asm volatile(
                        "st.async.shared::cluster.mbarrier::complete_tx::bytes.b64 "
                        "[%0], %1, [%2];"
                        :: "r"(rh), "l"(pk), "r"(rm) : "memory");
                }
            }
        }
        // no per-step cluster barrier
    }

    // final h arrived into buffer Tmax&1, signaled on mbar[Tmax&1]
    {
        uint32_t mf = (uint32_t)__cvta_generic_to_shared(&mbar[Tmax & 1]);
        mbar_wait_cluster(mf, (Tmax & 1) ? ph1 : ph0);
    }
    if (tid < 128) out[(size_t)myb * H_ + col] = hb[Tmax & 1][gb][col];

    // no CTA may exit while peers' st.async to our smem could be in flight
    asm volatile("barrier.cluster.arrive.aligned;" ::: "memory");
    asm volatile("barrier.cluster.wait.aligned;" ::: "memory");
}

// ======================= launch =======================
extern "C" void kernel_launch(void* const* d_in, const int* in_sizes, int n_in,
                              void* d_out, int out_size)
{
    const float* x       = (const float*)d_in[0];
    const float* att     = (const float*)d_in[1];
    const int*   lengths = (const int*)  d_in[2];
    const float* W_ih    = (const float*)d_in[3];
    const float* W_hh    = (const float*)d_in[4];
    const float* b_ih    = (const float*)d_in[5];
    const float* b_hh    = (const float*)d_in[6];
    float* out = (float*)d_out;
    (void)in_sizes; (void)n_in; (void)out_size;

    dim3 ggrid((B_ * T_) / BM, G3_ / BN);
    gi_gemm<<<ggrid, 256>>>(x, W_ih, b_ih, lengths);
    gru_rec<<<128, REC_THREADS>>>(att, lengths, W_hh, b_hh, out);
}